// round 12
// baseline (speedup 1.0000x reference)
#include <cuda_runtime.h>
#include <cuda_bf16.h>

// Level-3 Haar wavelet packet transform, freq (Gray-code) band order.
// x: [R=1024 rows, 65536], out: [R, 8 bands, 8192].
//
// natural band b=(l1,l2,l3): nat[b] = sum_j (-1)^(l1*j0+l2*j1+l3*j2) x[8k+j] * (1/sqrt2)^3
// output band i = nat[perm[i]], perm = [0,1,3,2,6,7,5,4].
//
// One-shot kernel (persistent grid-stride measured -23%: CTA replacement is
// the MLP engine). This round: 8 groups per thread (64 consecutive floats),
// 8x LDG.E.256 in, 8x STG.E.256 out (sm_100+ 256-bit stores; k multiple of 8
// -> 32B-aligned). Halves mem-instruction count per byte and doubles
// per-warp in-flight lines to keep the L1tex wavefront queue saturated.

#define GROUPS_PER_ROW 8192   // 65536 / 8
#define ROW_LEN        65536

__global__ void __launch_bounds__(256, 2)
WaveletPacketTransform_74715251081585_kernel(const float* __restrict__ x,
                                             float* __restrict__ out,
                                             int n_thread_units)  // total_groups / 8
{
    int t = blockIdx.x * blockDim.x + threadIdx.x;
    if (t >= n_thread_units) return;

    const int g0  = t << 3;                 // first group index (flat)
    const int k   = g0 & (GROUPS_PER_ROW - 1);
    const int row = g0 >> 13;               // g0 / 8192

    const float* __restrict__ xin = x + (size_t)g0 * 8;

    const float S = 0.35355339059327373f;   // (1/sqrt2)^3

    float r0[8], r1[8], r2[8], r3[8], r4[8], r5[8], r6[8], r7[8];

#pragma unroll
    for (int q = 0; q < 8; q++) {
        float v0, v1, v2, v3, v4, v5, v6, v7;
        // 256-bit read-only global load (sm_100+): one LDG.E.256 per group.
        asm("ld.global.nc.v8.f32 {%0,%1,%2,%3,%4,%5,%6,%7}, [%8];"
            : "=f"(v0), "=f"(v1), "=f"(v2), "=f"(v3),
              "=f"(v4), "=f"(v5), "=f"(v6), "=f"(v7)
            : "l"(xin + q * 8));

        // level 1: pairwise sum/diff
        float p0 = v0 + v1, m0 = v0 - v1;
        float p1 = v2 + v3, m1 = v2 - v3;
        float p2 = v4 + v5, m2 = v4 - v5;
        float p3 = v6 + v7, m3 = v6 - v7;

        // level 2
        float pp0 = p0 + p1, pm0 = p0 - p1;
        float pp1 = p2 + p3, pm1 = p2 - p3;
        float mp0 = m0 + m1, mm0 = m0 - m1;
        float mp1 = m2 + m3, mm1 = m2 - m3;

        // level 3 + Gray-code output permutation [0,1,3,2,6,7,5,4]
        r0[q] = (pp0 + pp1) * S;   // nat0 aaa
        r1[q] = (pp0 - pp1) * S;   // nat1 aad
        r2[q] = (pm0 - pm1) * S;   // nat3 add
        r3[q] = (pm0 + pm1) * S;   // nat2 ada
        r4[q] = (mm0 + mm1) * S;   // nat6 dda
        r5[q] = (mm0 - mm1) * S;   // nat7 ddd
        r6[q] = (mp0 - mp1) * S;   // nat5 dad
        r7[q] = (mp0 + mp1) * S;   // nat4 daa
    }

    float* __restrict__ ob = out + (size_t)row * ROW_LEN + k;
    // 256-bit streaming stores: one STG.E.256 per band (32B-aligned).
#define WR(i, a)                                                              \
    asm volatile("st.global.cs.v8.f32 [%0], {%1,%2,%3,%4,%5,%6,%7,%8};"      \
                 :: "l"(ob + (i) * GROUPS_PER_ROW),                           \
                    "f"(a[0]), "f"(a[1]), "f"(a[2]), "f"(a[3]),               \
                    "f"(a[4]), "f"(a[5]), "f"(a[6]), "f"(a[7])               \
                 : "memory")
    WR(0, r0); WR(1, r1); WR(2, r2); WR(3, r3);
    WR(4, r4); WR(5, r5); WR(6, r6); WR(7, r7);
#undef WR
}

extern "C" void kernel_launch(void* const* d_in, const int* in_sizes, int n_in,
                              void* d_out, int out_size)
{
    const float* x = (const float*)d_in[0];
    float* out = (float*)d_out;

    // total elements = 67,108,864; groups = /8; thread units = groups/8
    int n_thread_units = in_sizes[0] / 64;
    int block = 256;
    int grid = (n_thread_units + block - 1) / block;   // 4096 one-shot blocks
    WaveletPacketTransform_74715251081585_kernel<<<grid, block>>>(x, out, n_thread_units);
}

// round 13
// speedup vs baseline: 1.0352x; 1.0352x over previous
#include <cuda_runtime.h>
#include <cuda_bf16.h>

// Level-3 Haar wavelet packet transform, freq (Gray-code) band order.
// x: [R=1024 rows, 65536], out: [R, 8 bands, 8192].
//
// natural band b=(l1,l2,l3): nat[b] = sum_j (-1)^(l1*j0+l2*j1+l3*j2) x[8k+j] * (1/sqrt2)^3
// output band i = nat[perm[i]], perm = [0,1,3,2,6,7,5,4].
//
// FINAL configuration — best measured operating point (R11):
//  * one-shot kernel, 4096 blocks x 512 threads (persistent grid-stride
//    measured -23%: CTA replacement is the MLP engine);
//  * 4 consecutive groups per thread (32 floats) via 4x LDG.E.256
//    (sm_100+ 256-bit read-only loads, 128B-aligned per thread);
//  * one float4 store per band; per block each band's write burst is 8KB
//    contiguous; fully-written 128B lines, perfectly coalesced.
// Measured floor: ~6.2 TB/s HBM (78% DRAM-active), all SM pipes <12% —
// mixed read/write turnaround-limited; 8 g/t, evict_first, .cs isolation,
// and block-size variants all measured neutral or worse.

#define GROUPS_PER_ROW 8192   // 65536 / 8
#define ROW_LEN        65536

__global__ void __launch_bounds__(512, 3)
WaveletPacketTransform_74715251081585_kernel(const float* __restrict__ x,
                                             float* __restrict__ out,
                                             int n_thread_units)  // total_groups / 4
{
    int t = blockIdx.x * blockDim.x + threadIdx.x;
    if (t >= n_thread_units) return;

    const int g0  = t << 2;                 // first group index (flat)
    const int k   = g0 & (GROUPS_PER_ROW - 1);
    const int row = g0 >> 13;               // g0 / 8192

    const float* __restrict__ xin = x + (size_t)g0 * 8;

    const float S = 0.35355339059327373f;   // (1/sqrt2)^3

    float r0[4], r1[4], r2[4], r3[4], r4[4], r5[4], r6[4], r7[4];

#pragma unroll
    for (int q = 0; q < 4; q++) {
        float v0, v1, v2, v3, v4, v5, v6, v7;
        // 256-bit read-only global load (sm_100+): one LDG.E.256 per group.
        asm("ld.global.nc.v8.f32 {%0,%1,%2,%3,%4,%5,%6,%7}, [%8];"
            : "=f"(v0), "=f"(v1), "=f"(v2), "=f"(v3),
              "=f"(v4), "=f"(v5), "=f"(v6), "=f"(v7)
            : "l"(xin + q * 8));

        // level 1: pairwise sum/diff
        float p0 = v0 + v1, m0 = v0 - v1;
        float p1 = v2 + v3, m1 = v2 - v3;
        float p2 = v4 + v5, m2 = v4 - v5;
        float p3 = v6 + v7, m3 = v6 - v7;

        // level 2
        float pp0 = p0 + p1, pm0 = p0 - p1;
        float pp1 = p2 + p3, pm1 = p2 - p3;
        float mp0 = m0 + m1, mm0 = m0 - m1;
        float mp1 = m2 + m3, mm1 = m2 - m3;

        // level 3 + Gray-code output permutation [0,1,3,2,6,7,5,4]
        r0[q] = (pp0 + pp1) * S;   // nat0 aaa
        r1[q] = (pp0 - pp1) * S;   // nat1 aad
        r2[q] = (pm0 - pm1) * S;   // nat3 add
        r3[q] = (pm0 + pm1) * S;   // nat2 ada
        r4[q] = (mm0 + mm1) * S;   // nat6 dda
        r5[q] = (mm0 - mm1) * S;   // nat7 ddd
        r6[q] = (mp0 - mp1) * S;   // nat5 dad
        r7[q] = (mp0 + mp1) * S;   // nat4 daa
    }

    float* __restrict__ ob = out + (size_t)row * ROW_LEN + k;
    // Plain write-back STG.128 per band (fully-written lines; .cs isolated
    // this round — expected neutral, lets L2 aggregate write bursts).
#define WR(i, a) *reinterpret_cast<float4*>(ob + (i) * GROUPS_PER_ROW) = \
                     make_float4(a[0], a[1], a[2], a[3])
    WR(0, r0); WR(1, r1); WR(2, r2); WR(3, r3);
    WR(4, r4); WR(5, r5); WR(6, r6); WR(7, r7);
#undef WR
}

extern "C" void kernel_launch(void* const* d_in, const int* in_sizes, int n_in,
                              void* d_out, int out_size)
{
    const float* x = (const float*)d_in[0];
    float* out = (float*)d_out;

    // total elements = 67,108,864; groups = /8; thread units = groups/4
    int n_thread_units = in_sizes[0] / 32;
    int block = 512;
    int grid = (n_thread_units + block - 1) / block;   // 4096 one-shot blocks
    WaveletPacketTransform_74715251081585_kernel<<<grid, block>>>(x, out, n_thread_units);
}